// round 12
// baseline (speedup 1.0000x reference)
#include <cuda_runtime.h>
#include <stdint.h>

// Problem constants
#define BB 16
#define NN 25200
#define NV 6300              // NN / 4
#define CC 80
#define MAXDET 100

// Bucketed hi-subset (exact prefix of greedy; guarded fallback covers tails)
#define T_BKT 0.95f
#define NB 128               // buckets over [0.95, 1.0)
#define BSCALE 2560.0f       // NB / 0.05
#define BCAP 32              // per-bucket capacity (lambda ~9.8)
#define SCAP 2048            // sort buffer capacity (expected ~1260)
#define MCAP 1024            // conflict-matrix candidate cap (consumed ~500)

// Output layout (flattened concat, float32):
#define OFF_BOX   0
#define OFF_SCORE 6400
#define OFF_CLS   8000
#define OFF_CNT   136000

typedef unsigned long long ull;

// ---------------- scratch (__device__ globals: no allocs) -------------------
__device__ ull      g_skey[BB][MCAP];              // sorted top keys
__device__ __align__(16) unsigned g_bits[BB][MCAP][32];  // conflict rows (j>i)
__device__ int      g_len[BB];
__device__ int      g_bad[BB];
__device__ int      g_done[BB];
__device__ float4   g_cor[BB][NN];                 // fallback-only
__device__ float2   g_meta[BB][NN];                // fallback-only

// identical IOU expression everywhere (proven bit-exact vs reference)
__device__ __forceinline__ bool iou_conflict(float4 A, float aA, float4 B2, float aB)
{
    float ltx = fmaxf(A.x, B2.x);
    float lty = fmaxf(A.y, B2.y);
    float rbx = fminf(A.z, B2.z);
    float rby = fminf(A.w, B2.w);
    float w = fmaxf(rbx - ltx, 0.0f);
    float h = fmaxf(rby - lty, 0.0f);
    float inter = w * h;
    float denom = aA + aB - inter + 1e-9f;
    return inter > 0.5f * denom;
}

extern __shared__ ull dyn_smem[];

// =============================================================================
// K1: per-batch compact + bucket sort -> sorted top-MCAP keys to global.
// Dynamic smem: skey ull[SCAP] | bkey ull[NB*BCAP]  (48KB)
// =============================================================================
__global__ void __launch_bounds__(1024, 1)
sort_kernel(const float* __restrict__ obj)
{
    const int b    = blockIdx.x;
    const int tid  = threadIdx.x;
    const int wid  = tid >> 5;
    const int lane = tid & 31;

    ull* skey = dyn_smem;                  // [SCAP]
    ull* bkey = dyn_smem + SCAP;           // [NB*BCAP]

    __shared__ int s_cnt[NB];
    __shared__ int s_off[NB];
    __shared__ int s_ws[4];
    __shared__ int s_len;
    __shared__ int s_bad;

    const float4* obj4 = reinterpret_cast<const float4*>(obj) + (size_t)b * NV;

    // ---- phase A: smem bucket compaction -------------------------------------
    if (tid < NB) s_cnt[tid] = 0;
    if (tid == 0) s_bad = 0;
    __syncthreads();

    for (int i = tid; i < NV; i += 1024) {
        float4 s4 = obj4[i];
        #pragma unroll
        for (int j = 0; j < 4; j++) {
            float sc = (j == 0) ? s4.x : (j == 1) ? s4.y : (j == 2) ? s4.z : s4.w;
            if (sc >= T_BKT) {
                int n = i * 4 + j;
                int bk = (int)((sc - T_BKT) * BSCALE);
                bk = bk > (NB - 1) ? (NB - 1) : (bk < 0 ? 0 : bk);
                int pos = atomicAdd(&s_cnt[bk], 1);
                if (pos < BCAP) {
                    bkey[bk * BCAP + pos] = ((ull)__float_as_uint(sc) << 32)
                                          | (ull)(0xFFFFFFFFu - (unsigned)n);
                } else {
                    s_bad = 1;
                }
            }
        }
    }
    __syncthreads();

    // ---- phase B: descending-bucket offsets ----------------------------------
    int x = 0, v = 0;
    if (tid < NB) {
        v = s_cnt[NB - 1 - tid];
        x = v;
        #pragma unroll
        for (int o = 1; o < 32; o <<= 1) {
            int y = __shfl_up_sync(0xffffffffu, x, o);
            if (lane >= o) x += y;
        }
        if (lane == 31) s_ws[wid] = x;
    }
    __syncthreads();
    if (tid < NB) {
        int add = 0;
        #pragma unroll
        for (int w = 0; w < 4; w++) if (w < wid) add += s_ws[w];
        int incl = x + add;
        s_off[NB - 1 - tid] = incl - v;
        if (tid == NB - 1) s_len = incl;
    }
    __syncthreads();

    const int len = s_len;
    const int bad = (s_bad != 0) || (len > SCAP);

    if (!bad) {
        // ---- phase C: per-bucket in-warp bitonic sort32 ----------------------
        for (int bk = wid; bk < NB; bk += 32) {
            int n = s_cnt[bk];
            if (n == 0) continue;
            ull k = (lane < n) ? ~bkey[bk * BCAP + lane] : ~0ull;  // asc(~k)==desc(k)
            #pragma unroll
            for (int sz = 2; sz <= 32; sz <<= 1) {
                #pragma unroll
                for (int j = sz >> 1; j > 0; j >>= 1) {
                    ull pk = __shfl_xor_sync(0xffffffffu, k, j);
                    bool up = ((lane & sz) == 0);
                    bool takeMax = (((lane & j) != 0) == up);
                    if (takeMax ? (pk > k) : (pk < k)) k = pk;
                }
            }
            if (lane < n) skey[s_off[bk] + lane] = ~k;
        }
        __syncthreads();

        const int m = (len < MCAP) ? len : MCAP;
        if (tid < m) g_skey[b][tid] = skey[tid];
    }

    if (tid == 0) {
        g_len[b] = len;
        g_bad[b] = bad ? 1 : 0;
    }
}

// =============================================================================
// K2: chip-wide conflict-matrix build (upper triangle). grid (16 chunks, BB).
// Each CTA: gather all candidate corners to smem, compute 64 rows x MCAP cols.
// =============================================================================
__global__ void __launch_bounds__(1024)
matrix_kernel(const float* __restrict__ boxes)
{
    const int b   = blockIdx.y;
    const int tid = threadIdx.x;

    if (g_bad[b]) return;                       // uniform; fallback handles
    int len = g_len[b];
    if (len > MCAP) len = MCAP;

    __shared__ float4 cor4[MCAP];
    __shared__ float  sar[MCAP];

    const float4* bx4 = reinterpret_cast<const float4*>(boxes) + (size_t)b * NN;

    if (tid < len) {
        unsigned orig = 0xFFFFFFFFu - (unsigned)g_skey[b][tid];
        float4 vv = bx4[orig];                  // (x, y, w, h)
        float hx = 0.5f * vv.z;
        float hy = 0.5f * vv.w;
        float4 c = make_float4(vv.x - hx, vv.y - hy, vv.x + hx, vv.y + hy);
        cor4[tid] = c;
        sar[tid]  = (c.z - c.x) * (c.w - c.y);
    }
    __syncthreads();

    const int r = blockIdx.x * 64 + (tid >> 4);
    if (r >= len) return;

    const float4 cr = cor4[r];
    const float  ar = sar[r];
    const int c0 = (tid & 15) * 64;

    unsigned w0 = 0u, w1 = 0u;
    #pragma unroll 8
    for (int j = 0; j < 64; j++) {
        int col = c0 + j;
        if (col > r && col < len) {
            if (iou_conflict(cr, ar, cor4[col], sar[col])) {
                if (j < 32) w0 |= (1u << j);
                else        w1 |= (1u << (j - 32));
            }
        }
    }
    *reinterpret_cast<uint2*>(&g_bits[b][r][(tid & 15) * 2]) = make_uint2(w0, w1);
}

// =============================================================================
// K3: per-batch bitmap greedy resolve + fused output write.
// Dynamic smem: sbits unsigned[MCAP*32] (128KB) | skey_s ull[MCAP] (8KB)
// =============================================================================
__global__ void __launch_bounds__(1024, 1)
resolve_kernel(const float* __restrict__ boxes,
               const float* __restrict__ class_prob, float* __restrict__ out)
{
    const int b    = blockIdx.x;
    const int tid  = threadIdx.x;
    const int wid  = tid >> 5;
    const int lane = tid & 31;

    __shared__ int accList[MAXDET];
    __shared__ int s_acc;

    if (g_bad[b]) {
        if (tid == 0) g_done[b] = 0;
        return;                                 // fallback handles
    }
    int len = g_len[b];
    if (len > MCAP) len = MCAP;

    unsigned* sbits  = (unsigned*)dyn_smem;               // [MCAP*32]
    ull*      skey_s = (ull*)(sbits + MCAP * 32);         // [MCAP]

    // ---- load bitmap rows (<len) + keys to smem ------------------------------
    const int n4 = len * 8;                     // uint4 count (32 words/row)
    const uint4* src = reinterpret_cast<const uint4*>(&g_bits[b][0][0]);
    uint4* dst = reinterpret_cast<uint4*>(sbits);
    for (int t = tid; t < n4; t += 1024) dst[t] = src[t];
    if (tid < len) skey_s[tid] = g_skey[b][tid];
    __syncthreads();

    // ---- warp 0: bitmap greedy (exact: first alive == masked argmax) --------
    if (wid == 0) {
        int lo = lane << 5;
        unsigned alive = (len >= lo + 32) ? 0xffffffffu
                       : ((len <= lo) ? 0u : ((1u << (len - lo)) - 1u));
        int acc = 0;
        while (acc < MAXDET) {
            unsigned ball = __ballot_sync(0xffffffffu, alive != 0u);
            if (!ball) break;
            int wsel = __ffs(ball) - 1;
            unsigned w = __shfl_sync(0xffffffffu, alive, wsel);
            int bit = __ffs(w) - 1;
            int idx = (wsel << 5) + bit;
            if (lane == 0) accList[acc] = idx;
            acc++;
            unsigned rw = sbits[(idx << 5) + lane];   // conflict row (j>idx)
            alive &= ~rw;
            if (lane == wsel) alive &= ~(1u << bit);
        }
        if (lane == 0) s_acc = acc;
    }
    __syncthreads();

    const int acc = s_acc;
    if (tid == 0) g_done[b] = (acc == MAXDET) ? 1 : 0;
    if (acc != MAXDET) return;                  // fallback produces output

    // ---- fused output write --------------------------------------------------
    const float4* bx4 = reinterpret_cast<const float4*>(boxes) + (size_t)b * NN;

    if (tid < MAXDET) {
        int pos = accList[tid];
        ull k = skey_s[pos];
        unsigned orig = 0xFFFFFFFFu - (unsigned)k;
        float4 vv = bx4[orig];
        float hx = 0.5f * vv.z;
        float hy = 0.5f * vv.w;
        float4 c = make_float4(vv.x - hx, vv.y - hy, vv.x + hx, vv.y + hy);
        *reinterpret_cast<float4*>(out + OFF_BOX + (size_t)(b * MAXDET + tid) * 4) = c;
        out[OFF_SCORE + b * MAXDET + tid] = __uint_as_float((unsigned)(k >> 32));
    }
    for (int t = tid; t < MAXDET * (CC / 4); t += 1024) {
        int i  = t / (CC / 4);
        int sg = t - i * (CC / 4);
        unsigned orig = 0xFFFFFFFFu - (unsigned)skey_s[accList[i]];
        const float4* cp4 = reinterpret_cast<const float4*>(
            class_prob + ((size_t)b * NN + orig) * CC);
        float4* co4 = reinterpret_cast<float4*>(
            out + OFF_CLS + (size_t)(b * MAXDET + i) * CC);
        co4[sg] = cp4[sg];
    }
    if (tid == 0) out[OFF_CNT + b] = (float)MAXDET;
}

// =============================================================================
// K4: guarded exact fallback — ZERO dynamic smem (corners stay in global;
// statistically never runs the slow path, so its throughput is irrelevant).
// =============================================================================
__global__ void __launch_bounds__(1024, 1)
nms_fallback_kernel(const float* __restrict__ boxes, const float* __restrict__ obj,
                    const float* __restrict__ class_prob, float* __restrict__ out)
{
    const int b = blockIdx.x;
    if (g_done[b]) return;

    const int tid  = threadIdx.x;
    const int wid  = tid >> 5;
    const int lane = tid & 31;

    __shared__ ull  s_wkey[32];
    __shared__ int  s_wslot[32];
    __shared__ ull  s_winkey;
    __shared__ int  s_winslot;
    __shared__ int  s_base;
    __shared__ int  s_orig[MAXDET];

    const float4* bx4 = reinterpret_cast<const float4*>(boxes) + (size_t)b * NN;

    // ---- unordered compaction from raw inputs --------------------------------
    if (tid == 0) s_base = 0;
    __syncthreads();
    for (int st = 0; st < NN; st += 1024) {
        int n = st + tid;
        bool p = false;
        float sc = 0.0f;
        if (n < NN) {
            sc = obj[(size_t)b * NN + n];
            p = (sc >= 0.5f);
        }
        unsigned ball = __ballot_sync(0xffffffffu, p);
        int basew = 0;
        if (lane == 0 && ball) basew = atomicAdd(&s_base, __popc(ball));
        basew = __shfl_sync(0xffffffffu, basew, 0);
        if (p) {
            float4 vv = bx4[n];
            float hx = 0.5f * vv.z;
            float hy = 0.5f * vv.w;
            int pos = basew + __popc(ball & ((1u << lane) - 1u));
            g_cor[b][pos]  = make_float4(vv.x - hx, vv.y - hy, vv.x + hx, vv.y + hy);
            g_meta[b][pos] = make_float2(sc, __int_as_float(n));
        }
    }
    __syncthreads();
    const int cnt = s_base;

    // chunk mask: up to ceil(25200/1024)=25 chunks in a 32-bit mask
    const int kg_max = (cnt + 1023) >> 10;
    unsigned mask = 0u;
    for (int kg = 0; kg < kg_max; kg++) {
        if ((kg << 10) + tid < cnt) mask |= (1u << kg);
    }

    float4 W = make_float4(2.f, 2.f, 2.f, 2.f);   // overlaps nothing
    float Wa = 0.f;
    int ndet = 0;

    for (int it = 0; it < MAXDET; it++) {
        ull bk2 = 0ull;
        int bslot = 0;

        for (int kg = 0; kg < kg_max; kg++) {
            if ((mask >> kg) & 1u) {
                int slot = (kg << 10) + tid;
                float4 c = g_cor[b][slot];
                float a2 = (c.z - c.x) * (c.w - c.y);
                if (iou_conflict(W, Wa, c, a2)) {
                    mask &= ~(1u << kg);
                } else {
                    float2 m = g_meta[b][slot];
                    ull kk = ((ull)__float_as_uint(m.x) << 32)
                           | (ull)(0xFFFFFFFFu - __float_as_uint(m.y));
                    if (kk > bk2) { bk2 = kk; bslot = slot; }
                }
            }
        }

        #pragma unroll
        for (int off = 16; off; off >>= 1) {
            ull ok = __shfl_down_sync(0xffffffffu, bk2, off);
            int os = __shfl_down_sync(0xffffffffu, bslot, off);
            if (ok > bk2) { bk2 = ok; bslot = os; }
        }
        if (lane == 0) { s_wkey[wid] = bk2; s_wslot[wid] = bslot; }
        __syncthreads();

        if (wid == 0) {
            ull k2 = s_wkey[lane];
            int sl2 = s_wslot[lane];
            #pragma unroll
            for (int off = 16; off; off >>= 1) {
                ull ok = __shfl_down_sync(0xffffffffu, k2, off);
                int os = __shfl_down_sync(0xffffffffu, sl2, off);
                if (ok > k2) { k2 = ok; sl2 = os; }
            }
            if (lane == 0) { s_winkey = k2; s_winslot = sl2; }
        }
        __syncthreads();

        const ull wk = s_winkey;
        if (wk == 0ull) break;
        const int ws = s_winslot;

        W = g_cor[b][ws];                        // broadcast LDG
        Wa = (W.z - W.x) * (W.w - W.y);
        ndet = it + 1;

        if (tid == 0) {
            float* p = out + OFF_BOX + (size_t)(b * MAXDET + it) * 4;
            p[0] = W.x; p[1] = W.y; p[2] = W.z; p[3] = W.w;
            out[OFF_SCORE + b * MAXDET + it] =
                __uint_as_float((unsigned)(wk >> 32));
            s_orig[it] = (int)(0xFFFFFFFFu - (unsigned)wk);
        }
        if ((ws & 1023) == tid) mask &= ~(1u << (ws >> 10));   // self-clear
        __syncthreads();     // s_winkey protected before next round's writes
    }
    __syncthreads();

    for (int i = wid; i < MAXDET; i += 32) {
        bool valid = (i < ndet);
        int orig = valid ? s_orig[i] : 0;
        if (!valid && lane == 0) {
            float* p = out + OFF_BOX + (size_t)(b * MAXDET + i) * 4;
            p[0] = 0.f; p[1] = 0.f; p[2] = 0.f; p[3] = 0.f;
            out[OFF_SCORE + b * MAXDET + i] = 0.0f;
        }
        const float* cp = class_prob + ((size_t)b * NN + orig) * CC;
        float* co = out + OFF_CLS + (size_t)(b * MAXDET + i) * CC;
        #pragma unroll
        for (int c2 = lane; c2 < CC; c2 += 32) {
            co[c2] = valid ? cp[c2] : 0.0f;
        }
    }
    if (tid == 0) out[OFF_CNT + b] = (float)ndet;
}

// ---------------------------------------------------------------------------
extern "C" void kernel_launch(void* const* d_in, const int* in_sizes, int n_in,
                              void* d_out, int out_size)
{
    const float* boxes = (const float*)d_in[0];   // (16, 25200, 4)
    const float* obj   = (const float*)d_in[1];   // (16, 25200, 1)
    const float* cls   = (const float*)d_in[2];   // (16, 25200, 80)
    float* out = (float*)d_out;

    const int sortSmem = (SCAP + NB * BCAP) * (int)sizeof(ull);          // 48KB
    const int resSmem  = MCAP * 32 * (int)sizeof(unsigned)
                       + MCAP * (int)sizeof(ull);                        // 136KB

    static bool attr_done = false;
    if (!attr_done) {
        cudaFuncSetAttribute(sort_kernel,
                             cudaFuncAttributeMaxDynamicSharedMemorySize, sortSmem);
        cudaFuncSetAttribute(resolve_kernel,
                             cudaFuncAttributeMaxDynamicSharedMemorySize, resSmem);
        attr_done = true;
    }

    sort_kernel<<<BB, 1024, sortSmem>>>(obj);
    matrix_kernel<<<dim3(MCAP / 64, BB), 1024>>>(boxes);
    resolve_kernel<<<BB, 1024, resSmem>>>(boxes, cls, out);
    nms_fallback_kernel<<<BB, 1024>>>(boxes, obj, cls, out);
}

// round 13
// speedup vs baseline: 3.0778x; 3.0778x over previous
#include <cuda_runtime.h>
#include <stdint.h>

// Problem constants
#define BB 16
#define NN 25200
#define NV 6300              // NN / 4
#define CC 80
#define MAXDET 100

// Bucketed hi-subset (exact prefix of greedy; guarded fallback covers tails)
#define T_BKT 0.96f
#define NB 128               // buckets over [0.96, 1.0)
#define BSCALE 3200.0f       // NB / 0.04
#define BCAP 32              // per-bucket capacity (lambda ~7.9)
#define SCAP 2048            // sorted stream capacity (expected ~1008)
#define WIN 128              // walk window width

// Output layout (flattened concat, float32):
#define OFF_BOX   0
#define OFF_SCORE 6400
#define OFF_CLS   8000
#define OFF_CNT   136000

typedef unsigned long long ull;

// ---------------- scratch (__device__ globals: no allocs) -------------------
__device__ int    g_done[BB];
__device__ float4 g_cor[BB][NN];      // fallback-only
__device__ float2 g_meta[BB][NN];     // fallback-only

// identical IOU expression everywhere (proven bit-exact vs reference)
__device__ __forceinline__ bool iou_conflict(float4 A, float aA, float4 B2, float aB)
{
    float ltx = fmaxf(A.x, B2.x);
    float lty = fmaxf(A.y, B2.y);
    float rbx = fminf(A.z, B2.z);
    float rby = fminf(A.w, B2.w);
    float w = fmaxf(rbx - ltx, 0.0f);
    float h = fmaxf(rby - lty, 0.0f);
    float inter = w * h;
    float denom = aA + aB - inter + 1e-9f;
    return inter > 0.5f * denom;
}

extern __shared__ ull dyn_smem[];

// =============================================================================
// HOT kernel: compaction -> bucket sort -> gather -> windowed walk -> write.
// (structure identical to the proven 41.4us kernel; only T_BKT and the class
//  copy vectorization differ)
// Dynamic smem: skey ull[SCAP] | scor float4[SCAP] | sarea float[SCAP]
//               | bkey ull[NB*BCAP]   (~88KB)
// =============================================================================
__global__ void __launch_bounds__(1024, 1)
nms_hot_kernel(const float* __restrict__ boxes, const float* __restrict__ obj,
               const float* __restrict__ class_prob, float* __restrict__ out)
{
    const int b    = blockIdx.x;
    const int tid  = threadIdx.x;
    const int wid  = tid >> 5;
    const int lane = tid & 31;

    ull*    skey  = dyn_smem;                            // [SCAP]
    float4* scor  = (float4*)(dyn_smem + SCAP);          // [SCAP]
    float*  sarea = (float*)(scor + SCAP);               // [SCAP]
    ull*    bkey  = (ull*)(sarea + SCAP);                // [NB*BCAP]

    __shared__ int      s_cnt[NB];
    __shared__ int      s_off[NB];
    __shared__ int      s_ws[4];
    __shared__ int      s_len;
    __shared__ int      s_bad;
    __shared__ unsigned srow[WIN][4];
    __shared__ unsigned sconfA[4];
    __shared__ int      winPos[MAXDET];
    __shared__ float4   acor[MAXDET];
    __shared__ float    aarea[MAXDET];
    __shared__ int      s_accN;

    const float4* bx4  = reinterpret_cast<const float4*>(boxes) + (size_t)b * NN;
    const float4* obj4 = reinterpret_cast<const float4*>(obj) + (size_t)b * NV;

    // ================= phase A: smem bucket compaction =======================
    if (tid < NB) s_cnt[tid] = 0;
    if (tid < 4) sconfA[tid] = 0;
    if (tid == 0) { s_bad = 0; s_accN = 0; }
    __syncthreads();

    for (int i = tid; i < NV; i += 1024) {
        float4 s4 = obj4[i];
        #pragma unroll
        for (int j = 0; j < 4; j++) {
            float sc = (j == 0) ? s4.x : (j == 1) ? s4.y : (j == 2) ? s4.z : s4.w;
            if (sc >= T_BKT) {
                int n = i * 4 + j;
                int bk = (int)((sc - T_BKT) * BSCALE);
                bk = bk > (NB - 1) ? (NB - 1) : (bk < 0 ? 0 : bk);
                int pos = atomicAdd(&s_cnt[bk], 1);
                if (pos < BCAP) {
                    bkey[bk * BCAP + pos] = ((ull)__float_as_uint(sc) << 32)
                                          | (ull)(0xFFFFFFFFu - (unsigned)n);
                } else {
                    s_bad = 1;
                }
            }
        }
    }
    __syncthreads();

    // ================= phase B: descending-bucket offsets ====================
    int x = 0, v = 0;
    if (tid < NB) {
        v = s_cnt[NB - 1 - tid];
        x = v;
        #pragma unroll
        for (int o = 1; o < 32; o <<= 1) {
            int y = __shfl_up_sync(0xffffffffu, x, o);
            if (lane >= o) x += y;
        }
        if (lane == 31) s_ws[wid] = x;
    }
    __syncthreads();
    if (tid < NB) {
        int add = 0;
        #pragma unroll
        for (int w = 0; w < 4; w++) if (w < wid) add += s_ws[w];
        int incl = x + add;
        s_off[NB - 1 - tid] = incl - v;
        if (tid == NB - 1) s_len = incl;
    }
    __syncthreads();

    const int streamLen = s_len;
    if (s_bad || streamLen > SCAP) {
        if (tid == 0) g_done[b] = 0;
        return;
    }

    // ============ phase C: per-bucket in-warp bitonic sort32 =================
    for (int bk = wid; bk < NB; bk += 32) {
        int n = s_cnt[bk];
        if (n == 0) continue;
        ull k = (lane < n) ? ~bkey[bk * BCAP + lane] : ~0ull;  // asc(~k)==desc(k)
        #pragma unroll
        for (int sz = 2; sz <= 32; sz <<= 1) {
            #pragma unroll
            for (int j = sz >> 1; j > 0; j >>= 1) {
                ull pk = __shfl_xor_sync(0xffffffffu, k, j);
                bool up = ((lane & sz) == 0);
                bool takeMax = (((lane & j) != 0) == up);
                if (takeMax ? (pk > k) : (pk < k)) k = pk;
            }
        }
        if (lane < n) skey[s_off[bk] + lane] = ~k;
    }
    __syncthreads();

    // ============ phase D: gather corners + precompute areas =================
    for (int i = tid; i < streamLen; i += 1024) {
        int idx = (int)(0xFFFFFFFFu - (unsigned)skey[i]);
        float4 vv = bx4[idx];                       // (x, y, w, h)
        float hx = 0.5f * vv.z;
        float hy = 0.5f * vv.w;
        float4 c = make_float4(vv.x - hx, vv.y - hy, vv.x + hx, vv.y + hy);
        scor[i] = c;
        sarea[i] = (c.z - c.x) * (c.w - c.y);
    }
    __syncthreads();

    // ============ phase E: alive-filtered windowed greedy walk ===============
    const int r  = tid >> 3;      // 0..127 (window row)
    const int g8 = tid & 7;       // 0..7
    int accN = 0;

    for (int base = 0; base < streamLen && accN < MAXDET; base += WIN) {
        const int wcnt = (streamLen - base < WIN) ? (streamLen - base) : WIN;

        const bool rvalid = (r < wcnt);
        float4 cr = make_float4(0.f, 0.f, 0.f, 0.f);
        float  ar = 0.0f;
        if (rvalid) { cr = scor[base + r]; ar = sarea[base + r]; }

        // -- pass 1: conflicts vs previously accepted (8 threads/row) ---------
        bool conf = false;
        if (rvalid) {
            for (int a = g8; a < accN; a += 8) {
                if (iou_conflict(acor[a], aarea[a], cr, ar)) conf = true;
            }
        }
        unsigned bl = __ballot_sync(0xffffffffu, conf);
        if ((lane & 7) == 0) {
            if (((bl >> lane) & 0xffu) != 0u)
                atomicOr(&sconfA[r >> 5], 1u << (r & 31));
        }
        __syncthreads();                                           // B1

        // -- alive bitmap (dead = conflicted OR >= wcnt) ----------------------
        unsigned dead[4];
        #pragma unroll
        for (int w2 = 0; w2 < 4; w2++) {
            unsigned vm;
            int lo = w2 << 5;
            if (wcnt >= lo + 32) vm = 0xffffffffu;
            else if (wcnt <= lo) vm = 0u;
            else vm = (1u << (wcnt - lo)) - 1u;
            dead[w2] = sconfA[w2] | ~vm;
        }
        const bool ralive = rvalid && !((dead[r >> 5] >> (r & 31)) & 1u);

        // -- pass 2: pairwise rows (alive x alive); unconditional write -------
        unsigned bits = 0u;
        if (ralive) {
            int c0 = g8 * 16;
            #pragma unroll
            for (int j = 0; j < 16; j++) {
                int col = c0 + j;
                if (!((dead[col >> 5] >> (col & 31)) & 1u) && col != r) {
                    if (iou_conflict(cr, ar, scor[base + col], sarea[base + col]))
                        bits |= (1u << j);
                }
            }
        }
        unsigned hibits = __shfl_down_sync(0xffffffffu, bits, 1);
        if ((g8 & 1) == 0) srow[r][g8 >> 1] = bits | (hibits << 16);
        __syncthreads();                                           // B2

        // -- serial exact resolve (tid 0): indices only -----------------------
        if (tid == 0) {
            unsigned alive[4];
            #pragma unroll
            for (int w2 = 0; w2 < 4; w2++) alive[w2] = ~dead[w2];
            int acc = accN;
            #pragma unroll
            for (int w2 = 0; w2 < 4; w2++) {
                unsigned a = alive[w2];
                while (a && acc < MAXDET) {
                    int bit = __ffs(a) - 1;
                    a &= a - 1;
                    int i = (w2 << 5) + bit;
                    winPos[acc++] = base + i;
                    a &= ~srow[i][w2];
                    #pragma unroll
                    for (int w3 = 1; w3 < 4; w3++)
                        if (w3 > w2) alive[w3] &= ~srow[i][w3];
                }
                if (acc >= MAXDET) break;
            }
            s_accN = acc;
        }
        __syncthreads();                                           // B3

        // -- parallel copy of new accepts + clear sconfA for next window ------
        int newN = s_accN;
        for (int i = accN + tid; i < newN; i += 1024) {
            int sp = winPos[i];
            acor[i] = scor[sp];
            aarea[i] = sarea[sp];
        }
        if (tid < 4) sconfA[tid] = 0;
        __syncthreads();                                           // B4
        accN = newN;
    }

    if (tid == 0) g_done[b] = (accN == MAXDET) ? 1 : 0;
    if (accN != MAXDET) return;                 // fallback produces output

    // ============ phase F: fused output write (vectorized class copy) ========
    for (int i = wid; i < MAXDET; i += 32) {
        int pos = winPos[i];
        ull k = skey[pos];
        int orig = (int)(0xFFFFFFFFu - (unsigned)k);
        if (lane == 0) {
            float4 c = scor[pos];
            float* p = out + OFF_BOX + (size_t)(b * MAXDET + i) * 4;
            p[0] = c.x; p[1] = c.y; p[2] = c.z; p[3] = c.w;
            out[OFF_SCORE + b * MAXDET + i] = __uint_as_float((unsigned)(k >> 32));
        }
        const float4* cp4 = reinterpret_cast<const float4*>(
            class_prob + ((size_t)b * NN + orig) * CC);
        float4* co4 = reinterpret_cast<float4*>(
            out + OFF_CLS + (size_t)(b * MAXDET + i) * CC);
        if (lane < CC / 4) co4[lane] = cp4[lane];     // 20 x float4 per row
    }
    if (tid == 0) out[OFF_CNT + b] = (float)MAXDET;
}

// =============================================================================
// FALLBACK kernel (guarded by g_done) — ZERO dynamic smem (corners stay in
// global; statistically never runs the slow path, so throughput irrelevant).
// =============================================================================
__global__ void __launch_bounds__(1024, 1)
nms_fallback_kernel(const float* __restrict__ boxes, const float* __restrict__ obj,
                    const float* __restrict__ class_prob, float* __restrict__ out)
{
    const int b = blockIdx.x;
    if (g_done[b]) return;

    const int tid  = threadIdx.x;
    const int wid  = tid >> 5;
    const int lane = tid & 31;

    __shared__ ull  s_wkey[32];
    __shared__ int  s_wslot[32];
    __shared__ ull  s_winkey;
    __shared__ int  s_winslot;
    __shared__ int  s_base;
    __shared__ int  s_orig[MAXDET];

    const float4* bx4 = reinterpret_cast<const float4*>(boxes) + (size_t)b * NN;

    // ---- unordered compaction from raw inputs --------------------------------
    if (tid == 0) s_base = 0;
    __syncthreads();
    for (int st = 0; st < NN; st += 1024) {
        int n = st + tid;
        bool p = false;
        float sc = 0.0f;
        if (n < NN) {
            sc = obj[(size_t)b * NN + n];
            p = (sc >= 0.5f);
        }
        unsigned ball = __ballot_sync(0xffffffffu, p);
        int basew = 0;
        if (lane == 0 && ball) basew = atomicAdd(&s_base, __popc(ball));
        basew = __shfl_sync(0xffffffffu, basew, 0);
        if (p) {
            float4 vv = bx4[n];
            float hx = 0.5f * vv.z;
            float hy = 0.5f * vv.w;
            int pos = basew + __popc(ball & ((1u << lane) - 1u));
            g_cor[b][pos]  = make_float4(vv.x - hx, vv.y - hy, vv.x + hx, vv.y + hy);
            g_meta[b][pos] = make_float2(sc, __int_as_float(n));
        }
    }
    __syncthreads();
    const int cnt = s_base;

    // chunk mask: up to ceil(25200/1024)=25 chunks in a 32-bit mask
    const int kg_max = (cnt + 1023) >> 10;
    unsigned mask = 0u;
    for (int kg = 0; kg < kg_max; kg++) {
        if ((kg << 10) + tid < cnt) mask |= (1u << kg);
    }

    float4 W = make_float4(2.f, 2.f, 2.f, 2.f);   // overlaps nothing
    float Wa = 0.f;
    int ndet = 0;

    for (int it = 0; it < MAXDET; it++) {
        ull bk2 = 0ull;
        int bslot = 0;

        for (int kg = 0; kg < kg_max; kg++) {
            if ((mask >> kg) & 1u) {
                int slot = (kg << 10) + tid;
                float4 c = g_cor[b][slot];
                float a2 = (c.z - c.x) * (c.w - c.y);
                if (iou_conflict(W, Wa, c, a2)) {
                    mask &= ~(1u << kg);
                } else {
                    float2 m = g_meta[b][slot];
                    ull kk = ((ull)__float_as_uint(m.x) << 32)
                           | (ull)(0xFFFFFFFFu - __float_as_uint(m.y));
                    if (kk > bk2) { bk2 = kk; bslot = slot; }
                }
            }
        }

        #pragma unroll
        for (int off = 16; off; off >>= 1) {
            ull ok = __shfl_down_sync(0xffffffffu, bk2, off);
            int os = __shfl_down_sync(0xffffffffu, bslot, off);
            if (ok > bk2) { bk2 = ok; bslot = os; }
        }
        if (lane == 0) { s_wkey[wid] = bk2; s_wslot[wid] = bslot; }
        __syncthreads();

        if (wid == 0) {
            ull k2 = s_wkey[lane];
            int sl2 = s_wslot[lane];
            #pragma unroll
            for (int off = 16; off; off >>= 1) {
                ull ok = __shfl_down_sync(0xffffffffu, k2, off);
                int os = __shfl_down_sync(0xffffffffu, sl2, off);
                if (ok > k2) { k2 = ok; sl2 = os; }
            }
            if (lane == 0) { s_winkey = k2; s_winslot = sl2; }
        }
        __syncthreads();

        const ull wk = s_winkey;
        if (wk == 0ull) break;
        const int ws = s_winslot;

        W = g_cor[b][ws];                        // broadcast LDG
        Wa = (W.z - W.x) * (W.w - W.y);
        ndet = it + 1;

        if (tid == 0) {
            float* p = out + OFF_BOX + (size_t)(b * MAXDET + it) * 4;
            p[0] = W.x; p[1] = W.y; p[2] = W.z; p[3] = W.w;
            out[OFF_SCORE + b * MAXDET + it] =
                __uint_as_float((unsigned)(wk >> 32));
            s_orig[it] = (int)(0xFFFFFFFFu - (unsigned)wk);
        }
        if ((ws & 1023) == tid) mask &= ~(1u << (ws >> 10));   // self-clear
        __syncthreads();     // s_winkey protected before next round's writes
    }
    __syncthreads();

    for (int i = wid; i < MAXDET; i += 32) {
        bool valid = (i < ndet);
        int orig = valid ? s_orig[i] : 0;
        if (!valid && lane == 0) {
            float* p = out + OFF_BOX + (size_t)(b * MAXDET + i) * 4;
            p[0] = 0.f; p[1] = 0.f; p[2] = 0.f; p[3] = 0.f;
            out[OFF_SCORE + b * MAXDET + i] = 0.0f;
        }
        const float* cp = class_prob + ((size_t)b * NN + orig) * CC;
        float* co = out + OFF_CLS + (size_t)(b * MAXDET + i) * CC;
        #pragma unroll
        for (int c2 = lane; c2 < CC; c2 += 32) {
            co[c2] = valid ? cp[c2] : 0.0f;
        }
    }
    if (tid == 0) out[OFF_CNT + b] = (float)ndet;
}

// ---------------------------------------------------------------------------
extern "C" void kernel_launch(void* const* d_in, const int* in_sizes, int n_in,
                              void* d_out, int out_size)
{
    const float* boxes = (const float*)d_in[0];   // (16, 25200, 4)
    const float* obj   = (const float*)d_in[1];   // (16, 25200, 1)
    const float* cls   = (const float*)d_in[2];   // (16, 25200, 80)
    float* out = (float*)d_out;

    const int hotSmem = SCAP * (int)(sizeof(ull) + sizeof(float4) + sizeof(float))
                      + NB * BCAP * (int)sizeof(ull);                 // ~88KB

    static bool attr_done = false;
    if (!attr_done) {
        cudaFuncSetAttribute(nms_hot_kernel,
                             cudaFuncAttributeMaxDynamicSharedMemorySize, hotSmem);
        attr_done = true;
    }

    nms_hot_kernel<<<BB, 1024, hotSmem>>>(boxes, obj, cls, out);
    nms_fallback_kernel<<<BB, 1024>>>(boxes, obj, cls, out);
}

// round 14
// speedup vs baseline: 3.5658x; 1.1586x over previous
#include <cuda_runtime.h>
#include <stdint.h>

// Problem constants
#define BB 16
#define NN 25200
#define NV 6300              // NN / 4
#define CC 80
#define MAXDET 100

// Bucketed hi-subset (exact prefix of greedy; guarded fallback covers tails)
#define T_BKT 0.96f
#define NB 128               // buckets over [0.96, 1.0)
#define BSCALE 3200.0f       // NB / 0.04
#define BCAP 32              // per-bucket capacity (lambda ~7.9)
#define SCAP 2048            // sorted stream capacity (expected ~1008)
#define WIN 128              // walk window width

// Output layout (flattened concat, float32):
#define OFF_BOX   0
#define OFF_SCORE 6400
#define OFF_CLS   8000
#define OFF_CNT   136000

typedef unsigned long long ull;

// ---------------- scratch (__device__ globals: no allocs) -------------------
__device__ int    g_done[BB];
__device__ float4 g_cor[BB][NN];      // fallback-only
__device__ float2 g_meta[BB][NN];     // fallback-only

// identical IOU expression everywhere (proven bit-exact vs reference)
__device__ __forceinline__ bool iou_conflict(float4 A, float aA, float4 B2, float aB)
{
    float ltx = fmaxf(A.x, B2.x);
    float lty = fmaxf(A.y, B2.y);
    float rbx = fminf(A.z, B2.z);
    float rby = fminf(A.w, B2.w);
    float w = fmaxf(rbx - ltx, 0.0f);
    float h = fmaxf(rby - lty, 0.0f);
    float inter = w * h;
    float denom = aA + aB - inter + 1e-9f;
    return inter > 0.5f * denom;
}

extern __shared__ ull dyn_smem[];

// =============================================================================
// HOT kernel: compaction -> bucket sort -> gather -> windowed walk -> write.
// Dynamic smem: skey ull[SCAP] | scor float4[SCAP] | sarea float[SCAP]
//               | bkey ull[NB*BCAP]   (~88KB)
// =============================================================================
__global__ void __launch_bounds__(1024, 1)
nms_hot_kernel(const float* __restrict__ boxes, const float* __restrict__ obj,
               const float* __restrict__ class_prob, float* __restrict__ out)
{
    const int b    = blockIdx.x;
    const int tid  = threadIdx.x;
    const int wid  = tid >> 5;
    const int lane = tid & 31;

    ull*    skey  = dyn_smem;                            // [SCAP]
    float4* scor  = (float4*)(dyn_smem + SCAP);          // [SCAP]
    float*  sarea = (float*)(scor + SCAP);               // [SCAP]
    ull*    bkey  = (ull*)(sarea + SCAP);                // [NB*BCAP]

    __shared__ int      s_cnt[NB];
    __shared__ int      s_off[NB];
    __shared__ int      s_ws[4];
    __shared__ int      s_len;
    __shared__ int      s_bad;
    __shared__ unsigned srow[WIN][4];
    __shared__ unsigned sconfA[4];
    __shared__ int      winPos[MAXDET];
    __shared__ int      s_accN;

    const float4* bx4  = reinterpret_cast<const float4*>(boxes) + (size_t)b * NN;
    const float4* obj4 = reinterpret_cast<const float4*>(obj) + (size_t)b * NV;

    // ================= phase A: smem bucket compaction =======================
    if (tid < NB) s_cnt[tid] = 0;
    if (tid < 4) sconfA[tid] = 0;
    if (tid == 0) { s_bad = 0; s_accN = 0; }
    __syncthreads();

    for (int i = tid; i < NV; i += 1024) {
        float4 s4 = obj4[i];
        #pragma unroll
        for (int j = 0; j < 4; j++) {
            float sc = (j == 0) ? s4.x : (j == 1) ? s4.y : (j == 2) ? s4.z : s4.w;
            if (sc >= T_BKT) {
                int n = i * 4 + j;
                int bk = (int)((sc - T_BKT) * BSCALE);
                bk = bk > (NB - 1) ? (NB - 1) : (bk < 0 ? 0 : bk);
                int pos = atomicAdd(&s_cnt[bk], 1);
                if (pos < BCAP) {
                    bkey[bk * BCAP + pos] = ((ull)__float_as_uint(sc) << 32)
                                          | (ull)(0xFFFFFFFFu - (unsigned)n);
                } else {
                    s_bad = 1;
                }
            }
        }
    }
    __syncthreads();

    // ================= phase B: descending-bucket offsets ====================
    int x = 0, v = 0;
    if (tid < NB) {
        v = s_cnt[NB - 1 - tid];
        x = v;
        #pragma unroll
        for (int o = 1; o < 32; o <<= 1) {
            int y = __shfl_up_sync(0xffffffffu, x, o);
            if (lane >= o) x += y;
        }
        if (lane == 31) s_ws[wid] = x;
    }
    __syncthreads();
    if (tid < NB) {
        int add = 0;
        #pragma unroll
        for (int w = 0; w < 4; w++) if (w < wid) add += s_ws[w];
        int incl = x + add;
        s_off[NB - 1 - tid] = incl - v;
        if (tid == NB - 1) s_len = incl;
    }
    __syncthreads();

    const int streamLen = s_len;
    if (s_bad || streamLen > SCAP) {
        if (tid == 0) g_done[b] = 0;
        return;
    }

    // ============ phase C: per-bucket in-warp bitonic sort32 =================
    for (int bk = wid; bk < NB; bk += 32) {
        int n = s_cnt[bk];
        if (n == 0) continue;
        ull k = (lane < n) ? ~bkey[bk * BCAP + lane] : ~0ull;  // asc(~k)==desc(k)
        #pragma unroll
        for (int sz = 2; sz <= 32; sz <<= 1) {
            #pragma unroll
            for (int j = sz >> 1; j > 0; j >>= 1) {
                ull pk = __shfl_xor_sync(0xffffffffu, k, j);
                bool up = ((lane & sz) == 0);
                bool takeMax = (((lane & j) != 0) == up);
                if (takeMax ? (pk > k) : (pk < k)) k = pk;
            }
        }
        if (lane < n) skey[s_off[bk] + lane] = ~k;
    }
    __syncthreads();

    // ============ phase D: gather corners + precompute areas =================
    for (int i = tid; i < streamLen; i += 1024) {
        int idx = (int)(0xFFFFFFFFu - (unsigned)skey[i]);
        float4 vv = bx4[idx];                       // (x, y, w, h)
        float hx = 0.5f * vv.z;
        float hy = 0.5f * vv.w;
        float4 c = make_float4(vv.x - hx, vv.y - hy, vv.x + hx, vv.y + hy);
        scor[i] = c;
        sarea[i] = (c.z - c.x) * (c.w - c.y);
    }
    __syncthreads();

    // ============ phase E: alive-filtered windowed walk (3 barriers) =========
    const int r  = tid >> 3;      // 0..127 (window row)
    const int g8 = tid & 7;       // 0..7
    int accN = 0;

    for (int base = 0; base < streamLen && accN < MAXDET; base += WIN) {
        const int wcnt = (streamLen - base < WIN) ? (streamLen - base) : WIN;

        const bool rvalid = (r < wcnt);
        float4 cr = make_float4(0.f, 0.f, 0.f, 0.f);
        float  ar = 0.0f;
        if (rvalid) { cr = scor[base + r]; ar = sarea[base + r]; }

        // -- pass 1: conflicts vs accepted (via winPos indirection) -----------
        bool conf = false;
        if (rvalid) {
            for (int a = g8; a < accN; a += 8) {
                int sp = winPos[a];
                if (iou_conflict(scor[sp], sarea[sp], cr, ar)) conf = true;
            }
        }
        unsigned bl = __ballot_sync(0xffffffffu, conf);
        if ((lane & 7) == 0) {
            if (((bl >> lane) & 0xffu) != 0u)
                atomicOr(&sconfA[r >> 5], 1u << (r & 31));
        }
        __syncthreads();                                           // B1

        // -- alive bitmap (dead = conflicted OR >= wcnt) ----------------------
        unsigned dead[4];
        #pragma unroll
        for (int w2 = 0; w2 < 4; w2++) {
            unsigned vm;
            int lo = w2 << 5;
            if (wcnt >= lo + 32) vm = 0xffffffffu;
            else if (wcnt <= lo) vm = 0u;
            else vm = (1u << (wcnt - lo)) - 1u;
            dead[w2] = sconfA[w2] | ~vm;
        }
        const bool ralive = rvalid && !((dead[r >> 5] >> (r & 31)) & 1u);

        // -- pass 2: pairwise rows, UPPER TRIANGLE only (col > r) --------------
        unsigned bits = 0u;
        if (ralive) {
            int c0 = g8 * 16;
            #pragma unroll
            for (int j = 0; j < 16; j++) {
                int col = c0 + j;
                if (col > r && !((dead[col >> 5] >> (col & 31)) & 1u)) {
                    if (iou_conflict(cr, ar, scor[base + col], sarea[base + col]))
                        bits |= (1u << j);
                }
            }
        }
        unsigned hibits = __shfl_down_sync(0xffffffffu, bits, 1);
        if ((g8 & 1) == 0) srow[r][g8 >> 1] = bits | (hibits << 16);
        __syncthreads();                                           // B2

        // -- resolve (tid0, indices only) || warp1 clears sconfA ----------------
        if (tid == 0) {
            unsigned alive[4];
            #pragma unroll
            for (int w2 = 0; w2 < 4; w2++) alive[w2] = ~dead[w2];
            int acc = accN;
            #pragma unroll
            for (int w2 = 0; w2 < 4; w2++) {
                unsigned a = alive[w2];
                while (a && acc < MAXDET) {
                    int bit = __ffs(a) - 1;
                    a &= a - 1;
                    int i = (w2 << 5) + bit;
                    winPos[acc++] = base + i;
                    a &= ~srow[i][w2];
                    #pragma unroll
                    for (int w3 = 1; w3 < 4; w3++)
                        if (w3 > w2) alive[w3] &= ~srow[i][w3];
                }
                if (acc >= MAXDET) break;
            }
            s_accN = acc;
        } else if (tid >= 32 && tid < 36) {
            sconfA[tid - 32] = 0;                  // concurrent with resolve
        }
        __syncthreads();                                           // B3
        accN = s_accN;
    }

    if (tid == 0) g_done[b] = (accN == MAXDET) ? 1 : 0;
    if (accN != MAXDET) return;                 // fallback produces output

    // ============ phase F: fused output write (vectorized class copy) ========
    for (int i = wid; i < MAXDET; i += 32) {
        int pos = winPos[i];
        ull k = skey[pos];
        int orig = (int)(0xFFFFFFFFu - (unsigned)k);
        if (lane == 0) {
            float4 c = scor[pos];
            float* p = out + OFF_BOX + (size_t)(b * MAXDET + i) * 4;
            p[0] = c.x; p[1] = c.y; p[2] = c.z; p[3] = c.w;
            out[OFF_SCORE + b * MAXDET + i] = __uint_as_float((unsigned)(k >> 32));
        }
        const float4* cp4 = reinterpret_cast<const float4*>(
            class_prob + ((size_t)b * NN + orig) * CC);
        float4* co4 = reinterpret_cast<float4*>(
            out + OFF_CLS + (size_t)(b * MAXDET + i) * CC);
        if (lane < CC / 4) co4[lane] = cp4[lane];     // 20 x float4 per row
    }
    if (tid == 0) out[OFF_CNT + b] = (float)MAXDET;
}

// =============================================================================
// FALLBACK kernel (guarded by g_done) — ZERO dynamic smem (corners stay in
// global; statistically never runs the slow path, so throughput irrelevant).
// =============================================================================
__global__ void __launch_bounds__(1024, 1)
nms_fallback_kernel(const float* __restrict__ boxes, const float* __restrict__ obj,
                    const float* __restrict__ class_prob, float* __restrict__ out)
{
    const int b = blockIdx.x;
    if (g_done[b]) return;

    const int tid  = threadIdx.x;
    const int wid  = tid >> 5;
    const int lane = tid & 31;

    __shared__ ull  s_wkey[32];
    __shared__ int  s_wslot[32];
    __shared__ ull  s_winkey;
    __shared__ int  s_winslot;
    __shared__ int  s_base;
    __shared__ int  s_orig[MAXDET];

    const float4* bx4 = reinterpret_cast<const float4*>(boxes) + (size_t)b * NN;

    // ---- unordered compaction from raw inputs --------------------------------
    if (tid == 0) s_base = 0;
    __syncthreads();
    for (int st = 0; st < NN; st += 1024) {
        int n = st + tid;
        bool p = false;
        float sc = 0.0f;
        if (n < NN) {
            sc = obj[(size_t)b * NN + n];
            p = (sc >= 0.5f);
        }
        unsigned ball = __ballot_sync(0xffffffffu, p);
        int basew = 0;
        if (lane == 0 && ball) basew = atomicAdd(&s_base, __popc(ball));
        basew = __shfl_sync(0xffffffffu, basew, 0);
        if (p) {
            float4 vv = bx4[n];
            float hx = 0.5f * vv.z;
            float hy = 0.5f * vv.w;
            int pos = basew + __popc(ball & ((1u << lane) - 1u));
            g_cor[b][pos]  = make_float4(vv.x - hx, vv.y - hy, vv.x + hx, vv.y + hy);
            g_meta[b][pos] = make_float2(sc, __int_as_float(n));
        }
    }
    __syncthreads();
    const int cnt = s_base;

    // chunk mask: up to ceil(25200/1024)=25 chunks in a 32-bit mask
    const int kg_max = (cnt + 1023) >> 10;
    unsigned mask = 0u;
    for (int kg = 0; kg < kg_max; kg++) {
        if ((kg << 10) + tid < cnt) mask |= (1u << kg);
    }

    float4 W = make_float4(2.f, 2.f, 2.f, 2.f);   // overlaps nothing
    float Wa = 0.f;
    int ndet = 0;

    for (int it = 0; it < MAXDET; it++) {
        ull bk2 = 0ull;
        int bslot = 0;

        for (int kg = 0; kg < kg_max; kg++) {
            if ((mask >> kg) & 1u) {
                int slot = (kg << 10) + tid;
                float4 c = g_cor[b][slot];
                float a2 = (c.z - c.x) * (c.w - c.y);
                if (iou_conflict(W, Wa, c, a2)) {
                    mask &= ~(1u << kg);
                } else {
                    float2 m = g_meta[b][slot];
                    ull kk = ((ull)__float_as_uint(m.x) << 32)
                           | (ull)(0xFFFFFFFFu - __float_as_uint(m.y));
                    if (kk > bk2) { bk2 = kk; bslot = slot; }
                }
            }
        }

        #pragma unroll
        for (int off = 16; off; off >>= 1) {
            ull ok = __shfl_down_sync(0xffffffffu, bk2, off);
            int os = __shfl_down_sync(0xffffffffu, bslot, off);
            if (ok > bk2) { bk2 = ok; bslot = os; }
        }
        if (lane == 0) { s_wkey[wid] = bk2; s_wslot[wid] = bslot; }
        __syncthreads();

        if (wid == 0) {
            ull k2 = s_wkey[lane];
            int sl2 = s_wslot[lane];
            #pragma unroll
            for (int off = 16; off; off >>= 1) {
                ull ok = __shfl_down_sync(0xffffffffu, k2, off);
                int os = __shfl_down_sync(0xffffffffu, sl2, off);
                if (ok > k2) { k2 = ok; sl2 = os; }
            }
            if (lane == 0) { s_winkey = k2; s_winslot = sl2; }
        }
        __syncthreads();

        const ull wk = s_winkey;
        if (wk == 0ull) break;
        const int ws = s_winslot;

        W = g_cor[b][ws];                        // broadcast LDG
        Wa = (W.z - W.x) * (W.w - W.y);
        ndet = it + 1;

        if (tid == 0) {
            float* p = out + OFF_BOX + (size_t)(b * MAXDET + it) * 4;
            p[0] = W.x; p[1] = W.y; p[2] = W.z; p[3] = W.w;
            out[OFF_SCORE + b * MAXDET + it] =
                __uint_as_float((unsigned)(wk >> 32));
            s_orig[it] = (int)(0xFFFFFFFFu - (unsigned)wk);
        }
        if ((ws & 1023) == tid) mask &= ~(1u << (ws >> 10));   // self-clear
        __syncthreads();     // s_winkey protected before next round's writes
    }
    __syncthreads();

    for (int i = wid; i < MAXDET; i += 32) {
        bool valid = (i < ndet);
        int orig = valid ? s_orig[i] : 0;
        if (!valid && lane == 0) {
            float* p = out + OFF_BOX + (size_t)(b * MAXDET + i) * 4;
            p[0] = 0.f; p[1] = 0.f; p[2] = 0.f; p[3] = 0.f;
            out[OFF_SCORE + b * MAXDET + i] = 0.0f;
        }
        const float* cp = class_prob + ((size_t)b * NN + orig) * CC;
        float* co = out + OFF_CLS + (size_t)(b * MAXDET + i) * CC;
        #pragma unroll
        for (int c2 = lane; c2 < CC; c2 += 32) {
            co[c2] = valid ? cp[c2] : 0.0f;
        }
    }
    if (tid == 0) out[OFF_CNT + b] = (float)ndet;
}

// ---------------------------------------------------------------------------
extern "C" void kernel_launch(void* const* d_in, const int* in_sizes, int n_in,
                              void* d_out, int out_size)
{
    const float* boxes = (const float*)d_in[0];   // (16, 25200, 4)
    const float* obj   = (const float*)d_in[1];   // (16, 25200, 1)
    const float* cls   = (const float*)d_in[2];   // (16, 25200, 80)
    float* out = (float*)d_out;

    const int hotSmem = SCAP * (int)(sizeof(ull) + sizeof(float4) + sizeof(float))
                      + NB * BCAP * (int)sizeof(ull);                 // ~88KB

    static bool attr_done = false;
    if (!attr_done) {
        cudaFuncSetAttribute(nms_hot_kernel,
                             cudaFuncAttributeMaxDynamicSharedMemorySize, hotSmem);
        attr_done = true;
    }

    nms_hot_kernel<<<BB, 1024, hotSmem>>>(boxes, obj, cls, out);
    nms_fallback_kernel<<<BB, 1024>>>(boxes, obj, cls, out);
}